// round 17
// baseline (speedup 1.0000x reference)
#include <cuda_runtime.h>
#include <cuda_fp16.h>
#include <math.h>
#include <stdint.h>

// ---------------- problem constants ----------------
#define D_MODEL 2048
#define NHEADS  16
#define HD      128
#define BATCH   2
#define SEQ     2048
#define MROWS   (BATCH*SEQ)   // 4096
#define KT2     (2*D_MODEL)   // 4096 (2-term fp16 split along K)
#define BHS     (BATCH*NHEADS*SEQ)   // 65536

// fp16 GEMM operands: Xhat[4096,4096], AOhat[4096,4096], 4x What[2048,4096]
__device__ __half g_half[2ULL * MROWS * KT2 + 4ULL * D_MODEL * KT2];
// fp16 attention operands: Qhi,Qlo,Khi,Vhi each [B,H,S,HD]
__device__ __half g_attn[4ULL * BHS * HD];

// ---------------- PTX helpers (portable: sm_75/80-era only) ----------------
__device__ __forceinline__ uint32_t smem_u32(const void* p) {
    uint32_t r;
    asm("{ .reg .u64 t; cvta.to.shared.u64 t, %1; cvt.u32.u64 %0, t; }"
        : "=r"(r) : "l"(p));
    return r;
}

__device__ __forceinline__ void cp16(uint32_t dst, const void* src) {
    asm volatile("cp.async.cg.shared.global [%0], [%1], 16;"
                 :: "r"(dst), "l"(src));
}

__device__ __forceinline__ void ldsm_x4(uint32_t* r, uint32_t addr) {
    asm volatile("ldmatrix.sync.aligned.m8n8.x4.shared.b16 {%0,%1,%2,%3}, [%4];"
                 : "=r"(r[0]), "=r"(r[1]), "=r"(r[2]), "=r"(r[3]) : "r"(addr));
}

__device__ __forceinline__ void ldsm_x4_t(uint32_t* r, uint32_t addr) {
    asm volatile("ldmatrix.sync.aligned.m8n8.x4.trans.shared.b16 {%0,%1,%2,%3}, [%4];"
                 : "=r"(r[0]), "=r"(r[1]), "=r"(r[2]), "=r"(r[3]) : "r"(addr));
}

__device__ __forceinline__ void mma_f16(float* d, const uint32_t* a, const uint32_t* b) {
    asm volatile(
        "mma.sync.aligned.m16n8k16.row.col.f32.f16.f16.f32 "
        "{%0,%1,%2,%3}, {%4,%5,%6,%7}, {%8,%9}, {%0,%1,%2,%3};"
        : "+f"(d[0]), "+f"(d[1]), "+f"(d[2]), "+f"(d[3])
        : "r"(a[0]), "r"(a[1]), "r"(a[2]), "r"(a[3]), "r"(b[0]), "r"(b[1]));
}

__device__ __forceinline__ void pack_hilo(float a, float b, uint32_t& hi, uint32_t& lo) {
    __half2 th, tl;
    th.x = __float2half(a);
    th.y = __float2half(b);
    tl.x = __float2half(a - __half2float(th.x));
    tl.y = __float2half(b - __half2float(th.y));
    hi = *(uint32_t*)&th;
    lo = *(uint32_t*)&tl;
}

// ---------------- split fp32 -> 2-term fp16 ----------------
// A-side (isW=0): [hi | lo]    W-side (isW=1): [hi | hi]
__global__ __launch_bounds__(256) void split_kernel(
    const float* __restrict__ in, __half* __restrict__ out, int isW)
{
    int idx = blockIdx.x * 256 + threadIdx.x;
    int r = idx >> 11;
    int k = idx & 2047;
    float v = in[idx];
    __half hi = __float2half(v);
    __half lo = __float2half(v - __half2float(hi));
    __half* o = out + (size_t)r * KT2;
    o[k] = hi;
    o[D_MODEL + k] = isW ? hi : lo;
}

// ---------------- mma.sync fp16 GEMM: C = A @ B^T + bias ----------------
// mode 0: write fp32 C.   mode 1: RoPE -> Qhi,Qlo.   mode 2: RoPE -> Khi.
// mode 3: convert -> Vhi.   (modes 1-3 write [B,H,S,HD] fp16; BN==HD so
// each column tile is exactly one head and RoPE partner d^64 is in-tile.)
#define BM 128
#define BN 128
#define BK 32
#define NSTAGE 3
#define NT (KT2 / BK)                // 128
#define ROWB 80
#define A_BYTES (BM * ROWB)          // 10240
#define STAGE_BYTES (2 * BM * ROWB)  // 20480
#define TILE_F 132                   // fp32 epilogue tile row stride
#define GEMM_SMEM (BM * TILE_F * 4)  // 67584 > 3*STAGE_BYTES (61440)

__global__ __launch_bounds__(256) void gemm_mma_kernel(
    const __half* __restrict__ A, const __half* __restrict__ B,
    const float* __restrict__ bias, float* __restrict__ C,
    __half* __restrict__ H1, __half* __restrict__ H2, int mode)
{
    extern __shared__ __align__(128) char smraw[];
    const uint32_t smb = smem_u32(smraw);
    const int tid  = threadIdx.x;
    const int lane = tid & 31;
    const int wid  = tid >> 5;
    const int wm   = (wid >> 2) * 64;
    const int wn   = (wid & 3) * 32;
    const int rowBase = blockIdx.y * BM;
    const int colBase = blockIdx.x * BN;

    const char* Ag = (const char*)A + (size_t)rowBase * (KT2 * 2);
    const char* Bg = (const char*)B + (size_t)colBase * (KT2 * 2);

    float acc[4][4][4];
    #pragma unroll
    for (int mi = 0; mi < 4; mi++)
        #pragma unroll
        for (int ni = 0; ni < 4; ni++)
            #pragma unroll
            for (int u = 0; u < 4; u++) acc[mi][ni][u] = 0.f;

    const int lr0 = tid >> 2;
    const int lc  = (tid & 3) * 16;

    auto load_stage = [&](int kt) {
        if (kt < NT) {
            uint32_t base = smb + (kt % NSTAGE) * STAGE_BYTES;
            const size_t gk = (size_t)kt * 64;
            #pragma unroll
            for (int i = 0; i < 2; i++) {
                int r = lr0 + i * 64;
                cp16(base + r * ROWB + lc, Ag + (size_t)r * (KT2 * 2) + gk + lc);
            }
            #pragma unroll
            for (int i = 0; i < 2; i++) {
                int r = lr0 + i * 64;
                cp16(base + A_BYTES + r * ROWB + lc,
                     Bg + (size_t)r * (KT2 * 2) + gk + lc);
            }
        }
        asm volatile("cp.async.commit_group;" ::: "memory");
    };

    load_stage(0);
    load_stage(1);

    const int a_row  = lane & 15;
    const int a_half = (lane >> 4) * 16;
    const int b_row  = ((lane >> 4) << 3) + (lane & 7);
    const int b_half = ((lane >> 3) & 1) * 16;

    for (int kt = 0; kt < NT; kt++) {
        asm volatile("cp.async.wait_group %0;" :: "n"(NSTAGE - 2) : "memory");
        __syncthreads();
        load_stage(kt + NSTAGE - 1);

        uint32_t aBase = smb + (kt % NSTAGE) * STAGE_BYTES;
        uint32_t bBase = aBase + A_BYTES;

        #pragma unroll
        for (int j = 0; j < 2; j++) {
            uint32_t af[4][4];
            #pragma unroll
            for (int mi = 0; mi < 4; mi++)
                ldsm_x4(af[mi],
                        aBase + (wm + mi * 16 + a_row) * ROWB + j * 32 + a_half);
            uint32_t bf[2][4];
            #pragma unroll
            for (int nb = 0; nb < 2; nb++)
                ldsm_x4(bf[nb],
                        bBase + (wn + nb * 16 + b_row) * ROWB + j * 32 + b_half);
            #pragma unroll
            for (int mi = 0; mi < 4; mi++)
                #pragma unroll
                for (int ni = 0; ni < 4; ni++)
                    mma_f16(acc[mi][ni], af[mi], &bf[ni >> 1][(ni & 1) * 2]);
        }
        __syncthreads();
    }

    if (mode == 0) {
        // plain fp32 epilogue
        #pragma unroll
        for (int mi = 0; mi < 4; mi++) {
            int r0 = rowBase + wm + mi * 16 + (lane >> 2);
            #pragma unroll
            for (int ni = 0; ni < 4; ni++) {
                int cn = colBase + wn + ni * 8 + (lane & 3) * 2;
                float2 bv = *(const float2*)(bias + cn);
                float2 o0, o1;
                o0.x = acc[mi][ni][0] + bv.x; o0.y = acc[mi][ni][1] + bv.y;
                o1.x = acc[mi][ni][2] + bv.x; o1.y = acc[mi][ni][3] + bv.y;
                *(float2*)(C + (size_t)r0 * D_MODEL + cn) = o0;
                *(float2*)(C + (size_t)(r0 + 8) * D_MODEL + cn) = o1;
            }
        }
        return;
    }

    const int h = colBase >> 7;                // head for this tile

    if (mode == 3) {
        // V: direct fp16 convert, [B,H,S,HD]
        #pragma unroll
        for (int mi = 0; mi < 4; mi++) {
            int r0 = rowBase + wm + mi * 16 + (lane >> 2);
            int s0 = r0 & (SEQ - 1), b0 = r0 >> 11;
            int s1 = (r0 + 8) & (SEQ - 1), b1 = (r0 + 8) >> 11;
            __half* p0 = H1 + (((size_t)(b0 * NHEADS + h)) * SEQ + s0) * HD;
            __half* p1 = H1 + (((size_t)(b1 * NHEADS + h)) * SEQ + s1) * HD;
            #pragma unroll
            for (int ni = 0; ni < 4; ni++) {
                int cn = wn + ni * 8 + (lane & 3) * 2;
                float2 bv = *(const float2*)(bias + colBase + cn);
                __half2 v0, v1;
                v0.x = __float2half(acc[mi][ni][0] + bv.x);
                v0.y = __float2half(acc[mi][ni][1] + bv.y);
                v1.x = __float2half(acc[mi][ni][2] + bv.x);
                v1.y = __float2half(acc[mi][ni][3] + bv.y);
                *(__half2*)(p0 + cn) = v0;
                *(__half2*)(p1 + cn) = v1;
            }
        }
        return;
    }

    // modes 1,2: stage tile to smem fp32, then RoPE (reference-exact) + split
    float* smT = (float*)smraw;
    #pragma unroll
    for (int mi = 0; mi < 4; mi++) {
        int r0 = wm + mi * 16 + (lane >> 2);
        #pragma unroll
        for (int ni = 0; ni < 4; ni++) {
            int cn = wn + ni * 8 + (lane & 3) * 2;
            float2 bv = *(const float2*)(bias + colBase + cn);
            smT[r0 * TILE_F + cn]           = acc[mi][ni][0] + bv.x;
            smT[r0 * TILE_F + cn + 1]       = acc[mi][ni][1] + bv.y;
            smT[(r0 + 8) * TILE_F + cn]     = acc[mi][ni][2] + bv.x;
            smT[(r0 + 8) * TILE_F + cn + 1] = acc[mi][ni][3] + bv.y;
        }
    }
    __syncthreads();

    {
        int r = tid >> 1;                       // 0..127
        int cBase = (tid & 1) * 64;             // half owned by this thread
        int t = rowBase + r;
        int s = t & (SEQ - 1);
        int b = t >> 11;
        size_t rowIdx = (((size_t)(b * NHEADS + h)) * SEQ + s) * HD;
        #pragma unroll 8
        for (int cc = 0; cc < 64; cc += 2) {
            int d0 = cBase + cc;
            __half2 hiP, loP;
            #pragma unroll
            for (int e2 = 0; e2 < 2; e2++) {
                int d = d0 + e2;
                int j = d & 63;
                float invf = expf(-(float)j * (9.210340371976184f / 64.0f));
                float ang  = (float)s * invf;
                float e    = (d < 64) ? sinf(ang) : cosf(ang);   // emb quirk
                float ce   = cosf(e);
                float se   = sinf(e);
                float q  = smT[r * TILE_F + d];
                float qp = smT[r * TILE_F + (d ^ 64)];
                float sgn = (d < 64) ? -1.0f : 1.0f;
                float res = fmaf(q, ce, sgn * qp * se);
                __half hv = __float2half(res);
                if (e2 == 0) { hiP.x = hv; loP.x = __float2half(res - __half2float(hv)); }
                else         { hiP.y = hv; loP.y = __float2half(res - __half2float(hv)); }
            }
            *(__half2*)(H1 + rowIdx + d0) = hiP;
            if (mode == 1)
                *(__half2*)(H2 + rowIdx + d0) = loP;
        }
    }
}

// ---------------- tensor-core flash attention (fp16 2-term, R15-proven) ----------------
#define ATQ 128
#define ATK 64
#define AROWB 272
#define Q_ARR (ATQ * AROWB)            // 34816
#define KV_ARR (ATK * AROWB)           // 17408
#define KV_STAGE (2 * KV_ARR)          // 34816 (Khi, Vhi)
#define KV_OFF (2 * Q_ARR)             // 69632
#define ATTN_SMEM (KV_OFF + 2 * KV_STAGE)  // 139264
#define NKT (SEQ / ATK)                // 32

__global__ __launch_bounds__(256) void attn_mma_kernel(
    const __half* __restrict__ Qhi, const __half* __restrict__ Qlo,
    const __half* __restrict__ Khi, const __half* __restrict__ Vhi,
    __half* __restrict__ AOhat)     // [MROWS, KT2] in [hi | lo] layout
{
    extern __shared__ __align__(128) char smraw[];
    const uint32_t smb = smem_u32(smraw);
    const int tid  = threadIdx.x;
    const int lane = tid & 31;
    const int wid  = tid >> 5;
    const int qBase = blockIdx.x * ATQ;
    const int h = blockIdx.y;
    const int b = blockIdx.z;
    const size_t bh = (size_t)b * NHEADS + h;

    const char* Qhg = (const char*)Qhi + (bh * SEQ + qBase) * (HD * 2);
    const char* Qlg = (const char*)Qlo + (bh * SEQ + qBase) * (HD * 2);
    const char* Khg = (const char*)Khi + bh * SEQ * (HD * 2);
    const char* Vhg = (const char*)Vhi + bh * SEQ * (HD * 2);

    #pragma unroll
    for (int i = 0; i < 16; i++) {
        int idx = tid + i * 256;
        int arr = idx >> 11;
        int r   = (idx >> 4) & 127;
        int c   = (idx & 15) * 16;
        const char* sp = arr ? Qlg : Qhg;
        cp16(smb + arr * Q_ARR + r * AROWB + c, sp + (size_t)r * 256 + c);
    }
    asm volatile("cp.async.commit_group;" ::: "memory");

    auto loadKV = [&](int kt) {
        int s = kt & 1;
        #pragma unroll
        for (int i = 0; i < 8; i++) {
            int idx = tid + i * 256;
            int arr = idx >> 10;
            int r   = (idx >> 4) & 63;
            int c   = (idx & 15) * 16;
            const char* sp = arr ? Vhg : Khg;
            cp16(smb + KV_OFF + s * KV_STAGE + arr * KV_ARR + r * AROWB + c,
                 sp + (size_t)(kt * ATK + r) * 256 + c);
        }
        asm volatile("cp.async.commit_group;" ::: "memory");
    };

    loadKV(0);

    float oAcc[16][4];
    #pragma unroll
    for (int t2 = 0; t2 < 16; t2++)
        #pragma unroll
        for (int u = 0; u < 4; u++) oAcc[t2][u] = 0.f;
    float mA = -INFINITY, mB = -INFINITY, lA = 0.f, lB = 0.f;

    const int m0 = wid * 16;
    const int a_row  = lane & 15;
    const int a_halfB = (lane >> 4) * 16;
    const int b_row  = ((lane >> 4) << 3) + (lane & 7);
    const int b_halfB = ((lane >> 3) & 1) * 16;
    const float SCALE = 0.08838834764831845f;

    for (int kt = 0; kt < NKT; kt++) {
        if (kt + 1 < NKT) {
            loadKV(kt + 1);
            asm volatile("cp.async.wait_group 1;" ::: "memory");
        } else {
            asm volatile("cp.async.wait_group 0;" ::: "memory");
        }
        __syncthreads();

        const uint32_t kb   = smb + KV_OFF + (kt & 1) * KV_STAGE;
        const uint32_t KhiS = kb;
        const uint32_t VhiS = kb + KV_ARR;

        float sAcc[8][4];
        #pragma unroll
        for (int ni = 0; ni < 8; ni++)
            #pragma unroll
            for (int u = 0; u < 4; u++) sAcc[ni][u] = 0.f;

        #pragma unroll
        for (int j = 0; j < 8; j++) {
            uint32_t ah[4], al[4];
            uint32_t aoff = (m0 + a_row) * AROWB + j * 32 + a_halfB;
            ldsm_x4(ah, smb + aoff);
            ldsm_x4(al, smb + Q_ARR + aoff);
            uint32_t bh_[4][4];
            #pragma unroll
            for (int nb = 0; nb < 4; nb++)
                ldsm_x4(bh_[nb], KhiS + (nb * 16 + b_row) * AROWB + j * 32 + b_halfB);
            #pragma unroll
            for (int ni = 0; ni < 8; ni++) {
                const uint32_t* Bh = &bh_[ni >> 1][(ni & 1) * 2];
                mma_f16(sAcc[ni], ah, Bh);
                mma_f16(sAcc[ni], al, Bh);
            }
        }

        float mxA = -INFINITY, mxB = -INFINITY;
        #pragma unroll
        for (int ni = 0; ni < 8; ni++) {
            #pragma unroll
            for (int u = 0; u < 4; u++) sAcc[ni][u] *= SCALE;
            mxA = fmaxf(mxA, fmaxf(sAcc[ni][0], sAcc[ni][1]));
            mxB = fmaxf(mxB, fmaxf(sAcc[ni][2], sAcc[ni][3]));
        }
        mxA = fmaxf(mxA, __shfl_xor_sync(0xffffffff, mxA, 1));
        mxA = fmaxf(mxA, __shfl_xor_sync(0xffffffff, mxA, 2));
        mxB = fmaxf(mxB, __shfl_xor_sync(0xffffffff, mxB, 1));
        mxB = fmaxf(mxB, __shfl_xor_sync(0xffffffff, mxB, 2));

        float mAn = fmaxf(mA, mxA), mBn = fmaxf(mB, mxB);
        float cA = __expf(mA - mAn), cB = __expf(mB - mBn);
        mA = mAn; mB = mBn;

        float sumA = 0.f, sumB = 0.f;
        #pragma unroll
        for (int ni = 0; ni < 8; ni++) {
            sAcc[ni][0] = __expf(sAcc[ni][0] - mA);
            sAcc[ni][1] = __expf(sAcc[ni][1] - mA);
            sAcc[ni][2] = __expf(sAcc[ni][2] - mB);
            sAcc[ni][3] = __expf(sAcc[ni][3] - mB);
            sumA += sAcc[ni][0] + sAcc[ni][1];
            sumB += sAcc[ni][2] + sAcc[ni][3];
        }
        sumA += __shfl_xor_sync(0xffffffff, sumA, 1);
        sumA += __shfl_xor_sync(0xffffffff, sumA, 2);
        sumB += __shfl_xor_sync(0xffffffff, sumB, 1);
        sumB += __shfl_xor_sync(0xffffffff, sumB, 2);
        lA = lA * cA + sumA;
        lB = lB * cB + sumB;

        #pragma unroll
        for (int t2 = 0; t2 < 16; t2++) {
            oAcc[t2][0] *= cA; oAcc[t2][1] *= cA;
            oAcc[t2][2] *= cB; oAcc[t2][3] *= cB;
        }

        uint32_t phi[4][4], plo[4][4];
        #pragma unroll
        for (int j2 = 0; j2 < 4; j2++) {
            pack_hilo(sAcc[2*j2][0],   sAcc[2*j2][1],   phi[j2][0], plo[j2][0]);
            pack_hilo(sAcc[2*j2][2],   sAcc[2*j2][3],   phi[j2][1], plo[j2][1]);
            pack_hilo(sAcc[2*j2+1][0], sAcc[2*j2+1][1], phi[j2][2], plo[j2][2]);
            pack_hilo(sAcc[2*j2+1][2], sAcc[2*j2+1][3], phi[j2][3], plo[j2][3]);
        }

        #pragma unroll
        for (int j2 = 0; j2 < 4; j2++) {
            int key0 = j2 * 16;
            #pragma unroll
            for (int nb = 0; nb < 8; nb++) {
                uint32_t vh[4];
                uint32_t voff = (key0 + (lane & 15)) * AROWB
                              + (nb * 16 + ((lane >> 4) << 3)) * 2;
                ldsm_x4_t(vh, VhiS + voff);
                mma_f16(oAcc[2*nb],   phi[j2], vh);
                mma_f16(oAcc[2*nb],   plo[j2], vh);
                mma_f16(oAcc[2*nb+1], phi[j2], vh + 2);
                mma_f16(oAcc[2*nb+1], plo[j2], vh + 2);
            }
        }
        __syncthreads();
    }

    float invA = 1.0f / lA, invB = 1.0f / lB;
    int rA = qBase + m0 + (lane >> 2);
    int rB = rA + 8;
    __half* rowA = AOhat + (size_t)(b * SEQ + rA) * KT2 + h * HD;
    __half* rowB = AOhat + (size_t)(b * SEQ + rB) * KT2 + h * HD;
    #pragma unroll
    for (int t2 = 0; t2 < 16; t2++) {
        int cn = t2 * 8 + (lane & 3) * 2;
        float a0 = oAcc[t2][0] * invA, a1 = oAcc[t2][1] * invA;
        float b0 = oAcc[t2][2] * invB, b1 = oAcc[t2][3] * invB;
        uint32_t ahi, alo, bhi, blo;
        pack_hilo(a0, a1, ahi, alo);
        pack_hilo(b0, b1, bhi, blo);
        *(uint32_t*)(rowA + cn)           = ahi;
        *(uint32_t*)(rowA + D_MODEL + cn) = alo;
        *(uint32_t*)(rowB + cn)           = bhi;
        *(uint32_t*)(rowB + D_MODEL + cn) = blo;
    }
}

// ---------------- launch ----------------
extern "C" void kernel_launch(void* const* d_in, const int* in_sizes, int n_in,
                              void* d_out, int out_size)
{
    const float* x  = (const float*)d_in[0];
    const float* Wq = (const float*)d_in[1];
    const float* bq = (const float*)d_in[2];
    const float* Wk = (const float*)d_in[3];
    const float* bk = (const float*)d_in[4];
    const float* Wv = (const float*)d_in[5];
    const float* bv = (const float*)d_in[6];
    const float* Wo = (const float*)d_in[7];
    const float* bo = (const float*)d_in[8];
    float* out = (float*)d_out;

    __half* hp = nullptr;
    cudaGetSymbolAddress((void**)&hp, g_half);
    const size_t XH = (size_t)MROWS * KT2;
    const size_t WH = (size_t)D_MODEL * KT2;
    __half* Xhat  = hp;
    __half* AOhat = hp + XH;
    __half* WqH   = hp + 2 * XH;
    __half* WkH   = WqH + WH;
    __half* WvH   = WkH + WH;
    __half* WoH   = WvH + WH;

    __half* ap = nullptr;
    cudaGetSymbolAddress((void**)&ap, g_attn);
    const size_t AH = (size_t)BHS * HD;
    __half* Qhi = ap + 0 * AH;
    __half* Qlo = ap + 1 * AH;
    __half* Khi = ap + 2 * AH;
    __half* Vhi = ap + 3 * AH;

    cudaFuncSetAttribute(gemm_mma_kernel, cudaFuncAttributeMaxDynamicSharedMemorySize,
                         GEMM_SMEM);
    cudaFuncSetAttribute(attn_mma_kernel, cudaFuncAttributeMaxDynamicSharedMemorySize,
                         ATTN_SMEM);

    // split operands to 2-term fp16
    split_kernel<<<(MROWS * D_MODEL) / 256, 256>>>(x,  Xhat, 0);
    split_kernel<<<(D_MODEL * D_MODEL) / 256, 256>>>(Wq, WqH, 1);
    split_kernel<<<(D_MODEL * D_MODEL) / 256, 256>>>(Wk, WkH, 1);
    split_kernel<<<(D_MODEL * D_MODEL) / 256, 256>>>(Wv, WvH, 1);
    split_kernel<<<(D_MODEL * D_MODEL) / 256, 256>>>(Wo, WoH, 1);

    dim3 ggrid(D_MODEL / BN, MROWS / BM);   // (16, 32)
    // QKV GEMMs with fused RoPE/convert + fp16 split epilogues
    gemm_mma_kernel<<<ggrid, 256, GEMM_SMEM>>>(Xhat, WqH, bq, nullptr, Qhi, Qlo, 1);
    gemm_mma_kernel<<<ggrid, 256, GEMM_SMEM>>>(Xhat, WkH, bk, nullptr, Khi, nullptr, 2);
    gemm_mma_kernel<<<ggrid, 256, GEMM_SMEM>>>(Xhat, WvH, bv, nullptr, Vhi, nullptr, 3);

    attn_mma_kernel<<<dim3(SEQ / ATQ, NHEADS, BATCH), 256, ATTN_SMEM>>>(
        Qhi, Qlo, Khi, Vhi, AOhat);

    gemm_mma_kernel<<<ggrid, 256, GEMM_SMEM>>>(AOhat, WoH, bo, out, nullptr, nullptr, 0);
}